// round 1
// baseline (speedup 1.0000x reference)
#include <cuda_runtime.h>
#include <math.h>

#define HH 128
#define NPIX 16384
#define PI_F 3.14159265358979f

// Batch-independent per-pixel angle table (filled by init kernel each launch).
__device__ float g_theta[NPIX];

__global__ void init_theta_kernel() {
    int idx = blockIdx.x * blockDim.x + threadIdx.x;
    if (idx < NPIX) {
        float fi = (float)(idx >> 7) - 64.0f;   // xx - cx
        float fj = (float)(idx & 127) - 64.0f;  // yy - cy
        g_theta[idx] = atan2f(fj, fi);          // arctan2(yy-cy, xx-cx)
    }
}

// shared memory layout (floats)
#define SM_IMG  0
#define SM_SINX (16384)
#define SM_YACC (16384 + 128)
#define SM_G1   (16384 + 256)
#define SM_CBP  (16384 + 384)
#define SM_SIND (16384 + 512)
#define SM_RED  (16384 + 768)
#define SM_TOTAL (16384 + 768 + 32)

__global__ __launch_bounds__(256) void decode_kernel(
    const float* __restrict__ W,
    const float* __restrict__ ng,
    const float* __restrict__ nu,
    float* __restrict__ out)
{
    extern __shared__ float sm[];
    float* img_s = sm + SM_IMG;

    const int b = blockIdx.x;
    const int t = threadIdx.x;

    // ---- load weights (broadcast, L1) ----
    const float* Wb = W + b * 16;
    float w0  = __ldg(Wb + 0),  w1  = __ldg(Wb + 1),  w2  = __ldg(Wb + 2),  w3  = __ldg(Wb + 3);
    float w4  = __ldg(Wb + 4),  w5  = __ldg(Wb + 5),  w6  = __ldg(Wb + 6),  w7  = __ldg(Wb + 7);
    float w8  = __ldg(Wb + 8),  w9  = __ldg(Wb + 9),  w10 = __ldg(Wb + 10), w11 = __ldg(Wb + 11);
    float w12 = __ldg(Wb + 12), w13 = __ldg(Wb + 13), w14 = __ldg(Wb + 14), w15 = __ldg(Wb + 15);

    // ---- per-image params ----
    const float c0  = w0 * 6.0f;
    // central square half-size: non-fused mul/add to mirror reference evaluation at integer thresholds
    float hf = floorf(fminf(fmaxf(__fadd_rn(__fmul_rn(fabsf(w1), 8.0f), 2.0f), 2.0f), 12.0f));
    const int lo_ = 64 - (int)hf;
    const int hi_ = 64 + (int)hf;
    const float kx = w2 * (2.0f * PI_F / 128.0f);
    const float ky = w3 * (2.0f * PI_F / 128.0f);
    const float kd = w4 * (PI_F / 256.0f);          // arg = kd * (i + j)
    const float a5 = w5 * 10.0f;
    const float off = truncf(w7 * 5.0f);
    const float bxf = 64.0f + off;                   // bx == by
    const float sigma = 4.0f + fabsf(w7) * 5.0f;
    const float ninv = -0.5f / (sigma * sigma);
    const float rw8 = w8 * 10.0f;
    const float cb = floorf(fminf(fmaxf(__fadd_rn(__fmul_rn(fabsf(w9), 8.0f), 2.0f), 2.0f), 16.0f));
    const float invcb = 1.0f / cb;
    const float angle = w10 * PI_F;
    float sa, ca;
    sincosf(angle, &sa, &ca);
    const float k11 = w11 * 4.0f;
    const float k12 = 0.2f * w12;
    const float k13 = 0.2f * w13;

    // ---- fill 1-D tables (accurate lib math here; cost ~500 transcendentals/image) ----
    if (t < 128) {
        float tt = (float)t;
        sm[SM_SINX + t] = 0.5f * sinf(kx * tt);
        float db = tt - bxf;
        sm[SM_G1 + t] = expf(db * db * ninv);
        int ip = (int)floorf((tt + 0.5f) * invcb);   // == floor(t / cb) exactly for integer t, integer cb
        sm[SM_CBP + t] = (ip & 1) ? 0.3f : 0.0f;
        sm[SM_YACC + t] = 0.5f * sinf(ky * tt)
                        + 0.5f * sinf((tt + a5) * (PI_F / 128.0f))
                        + w6
                        - 0.5f * k13;                // fold (u-0.5)*k13 constant part
    }
    // diag sin table: indices 0..254 (fill 256)
    sm[SM_SIND + t] = 0.5f * sinf(kd * (float)t);
    __syncthreads();

    // ---- per-thread j-quad constants: thread owns columns j0..j0+3 for all rows ----
    const int j0 = (t & 31) * 4;
    float yaccl[4], gyl[4], cbq[4], dy2c[4], sady[4], sqh[4];
#pragma unroll
    for (int l = 0; l < 4; ++l) {
        int jl = j0 + l;
        float dyl = (float)jl - 64.0f;
        dy2c[l] = dyl * dyl;
        yaccl[l] = sm[SM_YACC + jl];
        gyl[l]  = sm[SM_G1 + jl];
        cbq[l]  = sm[SM_CBP + jl];
        sady[l] = sa * dyl;
        sqh[l]  = (jl >= lo_ && jl < hi_) ? 0.5f : 0.0f;
    }

    const float* ngb = ng + (size_t)b * NPIX;
    const float* nub = nu + (size_t)b * NPIX;

    float mnv = 3.4e38f, mxv = -3.4e38f;

    // ---- pass 1: compute image into smem, track min/max ----
#pragma unroll 2
    for (int k = 0; k < 16; ++k) {
        const int i = (t >> 5) + (k << 3);
        const int p = (i << 7) + j0;
        const float4 g4 = *(const float4*)(ngb + p);
        const float4 u4 = *(const float4*)(nub + p);
        const float4 th4 = *(const float4*)(g_theta + p);

        const float fi = (float)i;
        const float dx = fi - 64.0f;
        const float dx2 = dx * dx;
        const float sinxi = sm[SM_SINX + i];
        const float g1i = sm[SM_G1 + i];
        const float cbpi = sm[SM_CBP + i];
        const float xm = (i >= lo_ && i < hi_) ? 1.0f : 0.0f;
        const float cadx = ca * dx;
        const int sb = i + j0;

        float gq[4] = {g4.x, g4.y, g4.z, g4.w};
        float uq[4] = {u4.x, u4.y, u4.z, u4.w};
        float thq[4] = {th4.x, th4.y, th4.z, th4.w};
        float v[4];
#pragma unroll
        for (int l = 0; l < 4; ++l) {
            float r2 = dx2 + dy2c[l];
            float r = sqrtf(r2);
            float val = yaccl[l];
            // disk
            val += fminf(fmaxf(c0 - r, 0.0f), 1.0f);
            // central square
            val = fmaf(xm, sqh[l], val);
            // x-sinusoid (y-sinusoids folded into yacc)
            val += sinxi;
            // diagonal sinusoid
            val += sm[SM_SIND + sb + l];
            // gaussian blob (separable, bx == by)
            val = fmaf(g1i, gyl[l], val);
            // ring
            float tr = r - rw8;
            if (tr * tr < 10.0f) val += 1.0f;
            // checkerboard: XOR of parities via |a-b|, a,b in {0, 0.3}
            val += fabsf(cbpi - cbq[l]);
            // rotated line
            float rv = cadx + sady[l];
            if (fabsf(rv) < 3.0f) val += 0.6f;
            // angular sinusoid
            val = fmaf(0.5f, __sinf(thq[l] * k11), val);
            // noise
            val = fmaf(gq[l], k12, val);
            val = fmaf(uq[l], k13, val);

            mnv = fminf(mnv, val);
            mxv = fmaxf(mxv, val);
            v[l] = val;
        }
        *(float4*)(img_s + p) = make_float4(v[0], v[1], v[2], v[3]);
    }

    // ---- block min/max reduction ----
#pragma unroll
    for (int o = 16; o; o >>= 1) {
        mnv = fminf(mnv, __shfl_xor_sync(0xffffffffu, mnv, o));
        mxv = fmaxf(mxv, __shfl_xor_sync(0xffffffffu, mxv, o));
    }
    if ((t & 31) == 0) {
        sm[SM_RED + (t >> 5)] = mnv;
        sm[SM_RED + 8 + (t >> 5)] = mxv;
    }
    __syncthreads();
    if (t == 0) {
        float gmn = sm[SM_RED + 0], gmx = sm[SM_RED + 8];
#pragma unroll
        for (int wdx = 1; wdx < 8; ++wdx) {
            gmn = fminf(gmn, sm[SM_RED + wdx]);
            gmx = fmaxf(gmx, sm[SM_RED + 8 + wdx]);
        }
        // fold contrast (1+w14), optional inversion (w15>0), and min/max normalization
        // into a single affine out = (x - x0) * A  (exact algebra incl. the 1e-8 eps)
        float c = 1.0f + w14;
        float pp = (w15 > 0.0f) ? -c : c;
        float ap = fabsf(pp);
        float denom = (gmx - gmn) + 1e-8f / ap;      // ap==0 -> denom=inf -> A=0 -> out=0 (matches ref)
        float A = ((pp > 0.0f) ? 1.0f : -1.0f) / denom;
        float x0 = (pp > 0.0f) ? gmn : gmx;
        sm[SM_RED + 16] = A;
        sm[SM_RED + 17] = x0;
    }
    __syncthreads();
    const float A = sm[SM_RED + 16];
    const float C = -sm[SM_RED + 17] * A;

    // ---- pass 2: normalize + store ----
    float* outb = out + (size_t)b * NPIX;
#pragma unroll 2
    for (int k = 0; k < 16; ++k) {
        const int p = ((((t >> 5) + (k << 3))) << 7) + j0;
        float4 vv = *(const float4*)(img_s + p);
        vv.x = fmaf(vv.x, A, C);
        vv.y = fmaf(vv.y, A, C);
        vv.z = fmaf(vv.z, A, C);
        vv.w = fmaf(vv.w, A, C);
        *(float4*)(outb + p) = vv;
    }
}

extern "C" void kernel_launch(void* const* d_in, const int* in_sizes, int n_in,
                              void* d_out, int out_size) {
    const float* W  = (const float*)d_in[0];   // (2048, 16)
    const float* ng = (const float*)d_in[1];   // (2048, 128, 128)
    const float* nu = (const float*)d_in[2];   // (2048, 128, 128)
    float* out = (float*)d_out;                // (2048, 1, 128, 128)

    (void)in_sizes; (void)n_in; (void)out_size;

    const int smem_bytes = SM_TOTAL * sizeof(float);
    cudaFuncSetAttribute(decode_kernel, cudaFuncAttributeMaxDynamicSharedMemorySize, smem_bytes);

    init_theta_kernel<<<NPIX / 256, 256>>>();
    decode_kernel<<<2048, 256, smem_bytes>>>(W, ng, nu, out);
}